// round 7
// baseline (speedup 1.0000x reference)
#include <cuda_runtime.h>
#include <cuda_bf16.h>
#include <cuda_pipeline.h>

// CensoredLoss: outputs [B, T, V-1] f32, targets [B, T, V] f32, T=512, V=5.
// loss  = sum_{b,t} [ tgt0*log(1 - sum(out) + EPS) + sum_v tgt_{v+1}*log(out_v + EPS) ]
//         (masked rows have all-zero targets -> contribute exactly 0)
// count = #{(b,t) : sum_v targets[b,t,v] > 0}   (valid prefix => equals sum of lengths)
// result = count > 0 ? -loss/count : 0
//
// main: persistent grid (592 blocks) grid-striding over row-pairs, with
//       double-buffered smem staging of targets via cp.async so iteration i's
//       compute overlaps iteration i+1's loads. One reduction + 2 atomics per
//       block at the end.
// final: PDL-launched 1-thread kernel writes the scalar and resets accumulators.

#define T_DIM 512
#define V_DIM 5
#define RPB   2                          // rows per pair-iteration
#define PAIR_FLOATS (RPB * T_DIM * V_DIM)   // 5120 floats = 20 KB
#define EPSF  1e-8f
#define NTHREADS 512
#define GRID_PERSIST 592                 // 148 SMs * 4 blocks

__device__ double       g_loss;          // zero at module load; finalize re-zeros
__device__ unsigned int g_count;

__global__ __launch_bounds__(NTHREADS, 4)
void cl_main_kernel(const float* __restrict__ outputs,
                    const float* __restrict__ targets,
                    int npairs)
{
    __shared__ float s_tgt[2][PAIR_FLOATS];   // 2 x 20480 B double buffer
    __shared__ float s_sum[NTHREADS / 32];
    __shared__ int   s_cnt[NTHREADS / 32];

    // PDL primary-side trigger (dependent finalize may begin launching).
    asm volatile("griddepcontrol.launch_dependents;");

    const int tid    = threadIdx.x;
    const int t      = tid;              // timestep handled by this thread
    const int stride = gridDim.x;
    const float4* og4 = reinterpret_cast<const float4*>(outputs);

    float cAcc   = 0.0f;
    int   cntAcc = 0;

    // Prologue: stage first pair into buffer 0.
    int p0 = blockIdx.x;
    if (p0 < npairs) {
        const float4* src = reinterpret_cast<const float4*>(
            targets + (size_t)p0 * PAIR_FLOATS);
        float4* dst = reinterpret_cast<float4*>(s_tgt[0]);
        #pragma unroll
        for (int i = tid; i < PAIR_FLOATS / 4; i += NTHREADS)
            __pipeline_memcpy_async(&dst[i], &src[i], 16);
    }
    __pipeline_commit();

    int buf = 0;
    for (int p = p0; p < npairs; p += stride, buf ^= 1) {
        // Stage next pair into the other buffer (overlaps this iteration).
        const int pn = p + stride;
        if (pn < npairs) {
            const float4* src = reinterpret_cast<const float4*>(
                targets + (size_t)pn * PAIR_FLOATS);
            float4* dst = reinterpret_cast<float4*>(s_tgt[buf ^ 1]);
            #pragma unroll
            for (int i = tid; i < PAIR_FLOATS / 4; i += NTHREADS)
                __pipeline_memcpy_async(&dst[i], &src[i], 16);
        }
        __pipeline_commit();   // exactly one group per iteration (possibly empty)

        // Current pair's outputs records (float4, 16B aligned); issued before
        // the wait so they overlap the cp.async completion.
        const float4 o0 = og4[(size_t)(2 * p + 0) * T_DIM + t];
        const float4 o1 = og4[(size_t)(2 * p + 1) * T_DIM + t];

        __pipeline_wait_prior(1);   // current buffer's group complete
        __syncthreads();            // ... and visible to all threads

        const float* s = s_tgt[buf];
        {
            const float* q = s + t * 5;             // row 0 (conflict-free: gcd(5,32)=1)
            const float t0 = q[0], t1 = q[1], t2 = q[2], t3 = q[3], t4 = q[4];
            const float censor = 1.0f - (o0.x + o0.y + o0.z + o0.w);
            cAcc += t0 * __logf(censor + EPSF)
                  + t1 * __logf(o0.x + EPSF)
                  + t2 * __logf(o0.y + EPSF)
                  + t3 * __logf(o0.z + EPSF)
                  + t4 * __logf(o0.w + EPSF);
            cntAcc += ((t0 + t1 + t2 + t3 + t4) > 0.0f);
        }
        {
            const float* q = s + (T_DIM * V_DIM) + t * 5;   // row 1
            const float t0 = q[0], t1 = q[1], t2 = q[2], t3 = q[3], t4 = q[4];
            const float censor = 1.0f - (o1.x + o1.y + o1.z + o1.w);
            cAcc += t0 * __logf(censor + EPSF)
                  + t1 * __logf(o1.x + EPSF)
                  + t2 * __logf(o1.y + EPSF)
                  + t3 * __logf(o1.z + EPSF)
                  + t4 * __logf(o1.w + EPSF);
            cntAcc += ((t0 + t1 + t2 + t3 + t4) > 0.0f);
        }

        __syncthreads();   // all threads done reading buf before it is restaged
    }

    // Block reduction (once per block), then fire-and-forget atomics.
    #pragma unroll
    for (int off = 16; off > 0; off >>= 1) {
        cAcc   += __shfl_down_sync(0xffffffffu, cAcc, off);
        cntAcc += __shfl_down_sync(0xffffffffu, cntAcc, off);
    }
    if ((tid & 31) == 0) {
        s_sum[tid >> 5] = cAcc;
        s_cnt[tid >> 5] = cntAcc;
    }
    __syncthreads();
    if (tid < NTHREADS / 32) {
        cAcc   = s_sum[tid];
        cntAcc = s_cnt[tid];
        #pragma unroll
        for (int off = (NTHREADS / 64); off > 0; off >>= 1) {
            cAcc   += __shfl_down_sync(0xffffu, cAcc, off);
            cntAcc += __shfl_down_sync(0xffffu, cntAcc, off);
        }
        if (tid == 0) {
            atomicAdd(&g_loss, (double)cAcc);
            atomicAdd(&g_count, (unsigned int)cntAcc);
        }
    }
}

__global__ void cl_final_kernel(float* __restrict__ out) {
    // PDL dependent side: all primary-grid memory ops visible after this.
    asm volatile("griddepcontrol.wait;" ::: "memory");

    const double loss      = g_loss;
    const unsigned int cnt = g_count;
    out[0] = (cnt > 0u) ? (float)(-loss / (double)cnt) : 0.0f;
    // Reset for the next graph replay (deterministic by induction).
    g_loss  = 0.0;
    g_count = 0u;
}

extern "C" void kernel_launch(void* const* d_in, const int* in_sizes, int n_in,
                              void* d_out, int out_size)
{
    const float* outputs = (const float*)d_in[0];
    const float* targets = (const float*)d_in[1];
    float* out = (float*)d_out;

    const int B      = in_sizes[1] / (T_DIM * V_DIM);   // 16384
    const int npairs = B / RPB;                          // 8192
    const int grid   = (npairs < GRID_PERSIST) ? npairs : GRID_PERSIST;

    cl_main_kernel<<<grid, NTHREADS>>>(outputs, targets, npairs);

    // Finalize (PDL; degrades to plain serialization if the edge is ignored).
    cudaLaunchConfig_t cfg = {};
    cfg.gridDim  = dim3(1, 1, 1);
    cfg.blockDim = dim3(1, 1, 1);
    cfg.dynamicSmemBytes = 0;
    cfg.stream = 0;
    cudaLaunchAttribute attrs[1];
    attrs[0].id = cudaLaunchAttributeProgrammaticStreamSerialization;
    attrs[0].val.programmaticStreamSerializationAllowed = 1;
    cfg.attrs    = attrs;
    cfg.numAttrs = 1;
    cudaLaunchKernelEx(&cfg, cl_final_kernel, out);
}

// round 9
// speedup vs baseline: 1.0417x; 1.0417x over previous
#include <cuda_runtime.h>
#include <cuda_bf16.h>

// CensoredLoss: outputs [B, T, V-1] f32, targets [B, T, V] f32, T=512, V=5.
// loss  = sum_{b,t} [ tgt0*log(1 - sum(out) + EPS) + sum_v tgt_{v+1}*log(out_v + EPS) ]
//         (masked rows have all-zero targets -> contribute exactly 0)
// count = #{(b,t) : sum_v targets[b,t,v] > 0}   (valid prefix => sum of lengths)
// result = count > 0 ? -loss/count : 0
//
// main: 4 rows/block (R4 shape, doubled): prefetch 4 output float4s, stage
//       4 target rows through smem with coalesced float4 loads, one block
//       reduction + 2 fire-and-forget atomics.
// final: separate 1-thread kernel writes the scalar and resets accumulators
//        (fixed ~5us graph-node tax; PDL/ticket variants measured worse).

#define T_DIM 512
#define V_DIM 5
#define RPB   4                       // rows per block
#define ROW_FLOATS (T_DIM * V_DIM)    // 2560
#define EPSF  1e-8f
#define NTHREADS 512

__device__ double       g_loss;       // zero at module load; finalize re-zeros
__device__ unsigned int g_count;

__global__ __launch_bounds__(NTHREADS, 4)
void cl_main_kernel(const float* __restrict__ outputs,
                    const float* __restrict__ targets)
{
    __shared__ float s_tgt[RPB * ROW_FLOATS];      // 40960 B, four rows of targets
    __shared__ float s_sum[NTHREADS / 32];
    __shared__ int   s_cnt[NTHREADS / 32];

    const int b0  = blockIdx.x * RPB;
    const int tid = threadIdx.x;
    const int t   = tid;                            // one timestep per thread per row

    // Prefetch all four rows' outputs records (float4, 16B aligned) first so
    // their DRAM latency overlaps the targets staging.
    const float4* og4 = reinterpret_cast<const float4*>(outputs);
    const float4 o0 = og4[(size_t)(b0 + 0) * T_DIM + t];
    const float4 o1 = og4[(size_t)(b0 + 1) * T_DIM + t];
    const float4 o2 = og4[(size_t)(b0 + 2) * T_DIM + t];
    const float4 o3 = og4[(size_t)(b0 + 3) * T_DIM + t];

    // Stage 4 rows of targets via fully-coalesced float4 loads (rows adjacent;
    // block base = b0 * 2560 floats = b0 * 10240 B -> 16B aligned).
    const float4* tg4 = reinterpret_cast<const float4*>(
        targets + (size_t)b0 * ROW_FLOATS);
    float4* s4 = reinterpret_cast<float4*>(s_tgt);
    #pragma unroll
    for (int i = tid; i < (RPB * ROW_FLOATS) / 4; i += NTHREADS)
        s4[i] = tg4[i];
    __syncthreads();

    float c   = 0.0f;
    int   cnt = 0;

    #pragma unroll
    for (int r = 0; r < RPB; r++) {
        const float4 o = (r == 0) ? o0 : (r == 1) ? o1 : (r == 2) ? o2 : o3;
        const float* q = s_tgt + r * ROW_FLOATS + t * 5;   // conflict-free: gcd(5,32)=1
        const float t0 = q[0], t1 = q[1], t2 = q[2], t3 = q[3], t4 = q[4];
        const float censor = 1.0f - (o.x + o.y + o.z + o.w);
        c += t0 * __logf(censor + EPSF)
           + t1 * __logf(o.x + EPSF)
           + t2 * __logf(o.y + EPSF)
           + t3 * __logf(o.z + EPSF)
           + t4 * __logf(o.w + EPSF);
        cnt += ((t0 + t1 + t2 + t3 + t4) > 0.0f);
    }

    // Warp reduction.
    #pragma unroll
    for (int off = 16; off > 0; off >>= 1) {
        c   += __shfl_down_sync(0xffffffffu, c, off);
        cnt += __shfl_down_sync(0xffffffffu, cnt, off);
    }
    if ((tid & 31) == 0) {
        s_sum[tid >> 5] = c;
        s_cnt[tid >> 5] = cnt;
    }
    __syncthreads();

    // Final reduce across 16 warps (lanes 0..15 of warp 0), then RED atomics
    // (returns unused -> fire-and-forget reductions, no round-trip wait).
    if (tid < NTHREADS / 32) {
        c   = s_sum[tid];
        cnt = s_cnt[tid];
        #pragma unroll
        for (int off = (NTHREADS / 64); off > 0; off >>= 1) {
            c   += __shfl_down_sync(0xffffu, c, off);
            cnt += __shfl_down_sync(0xffffu, cnt, off);
        }
        if (tid == 0) {
            atomicAdd(&g_loss, (double)c);
            atomicAdd(&g_count, (unsigned int)cnt);
        }
    }
}

__global__ void cl_final_kernel(float* __restrict__ out) {
    const double loss      = g_loss;
    const unsigned int cnt = g_count;
    out[0] = (cnt > 0u) ? (float)(-loss / (double)cnt) : 0.0f;
    // Reset for the next graph replay (deterministic by induction).
    g_loss  = 0.0;
    g_count = 0u;
}

extern "C" void kernel_launch(void* const* d_in, const int* in_sizes, int n_in,
                              void* d_out, int out_size)
{
    const float* outputs = (const float*)d_in[0];
    const float* targets = (const float*)d_in[1];
    float* out = (float*)d_out;

    const int B = in_sizes[1] / ROW_FLOATS;        // 16384

    cl_main_kernel<<<B / RPB, NTHREADS>>>(outputs, targets);
    cl_final_kernel<<<1, 1>>>(out);
}